// round 16
// baseline (speedup 1.0000x reference)
#include <cuda_runtime.h>
#include <cuda_fp16.h>
#include <math.h>
#include <stdint.h>

#define N_TOK    16384
#define HID      4096
#define NE       64
#define TM       128
#define NTHREADS 256
#define NBLK     (N_TOK/TM)          // 128

// K split between pipes: tensor 48 cyc/k vs fma 64 cyc/k per SMSP
#define K_T      2368                // tensor-path K (74 tiles of 32)
#define NT_T     (K_T/32)            // 74
#define K_F      (HID-K_T)           // 1728 fma-path K
#define NT_F     (K_F/64)            // 27 tiles of 64
#define KP_F     (K_F/2)             // 864 k-pairs

#define LO_SCALE   2048.0f
#define LO_UNSCALE (1.0f/2048.0f)

// ---- smem layout ----
#define SM_RED   0
#define T_OFF    1024
#define TA_HI    0
#define TA_LO    10240               // 128 rows x 80B
#define TB_HI    20480
#define TB_LO    25600               // 64 rows x 80B
#define T_BUF    30720
#define FA_OFF   (T_OFF + 2*T_BUF)   // 62464
#define FA_ROW   272                 // 64 f32 + pad (16B aligned)
#define FA_BUF   (128*FA_ROW)        // 34816
#define FB_OFF   (FA_OFF + 2*FA_BUF) // 132096
#define FB_ROW   560                 // 4 groups x 128B @ 144B offsets
#define FB_BUF   (32*FB_ROW)         // 17920
#define SMEM_TOTAL (FB_OFF + 2*FB_BUF) // 167936
#define LS_OFF   FA_OFF              // epilogue logits 128x65 f32

// B pre-transposed k-pair-major for the fma slice: [kp][e] float2
__device__ __align__(16) float2 g_Bt[KP_F * NE];

__device__ float g_Pp[NBLK * NE];
__device__ float g_cp[NBLK * NE];
__device__ float g_zp[NBLK];
__device__ unsigned int g_arrive = 0;

__device__ __forceinline__ uint32_t smem_u32(const void* p) {
    uint32_t a;
    asm("{ .reg .u64 t; cvta.to.shared.u64 t, %1; cvt.u32.u64 %0, t; }" : "=r"(a) : "l"(p));
    return a;
}
__device__ __forceinline__ void mma_f32(float* c, const uint32_t* a, const uint32_t* b) {
    asm volatile(
        "mma.sync.aligned.m16n8k16.row.col.f32.f16.f16.f32 "
        "{%0,%1,%2,%3}, {%4,%5,%6,%7}, {%8,%9}, {%0,%1,%2,%3};"
        : "+f"(c[0]), "+f"(c[1]), "+f"(c[2]), "+f"(c[3])
        : "r"(a[0]), "r"(a[1]), "r"(a[2]), "r"(a[3]), "r"(b[0]), "r"(b[1]));
}
__device__ __forceinline__ void mma_f16(uint32_t* c, const uint32_t* a, const uint32_t* b) {
    asm volatile(
        "mma.sync.aligned.m16n8k16.row.col.f16.f16.f16.f16 "
        "{%0,%1}, {%2,%3,%4,%5}, {%6,%7}, {%0,%1};"
        : "+r"(c[0]), "+r"(c[1])
        : "r"(a[0]), "r"(a[1]), "r"(a[2]), "r"(a[3]), "r"(b[0]), "r"(b[1]));
}
#define LDSM4(r, addr)                                                           \
    asm volatile("ldmatrix.sync.aligned.m8n8.x4.shared.b16 {%0,%1,%2,%3}, [%4];" \
        : "=r"((r)[0]), "=r"((r)[1]), "=r"((r)[2]), "=r"((r)[3]) : "r"(addr))
__device__ __forceinline__ void fma2(unsigned long long &d, unsigned long long a,
                                     unsigned long long b) {
    asm("fma.rn.f32x2 %0, %1, %2, %0;" : "+l"(d) : "l"(a), "l"(b));
}
__device__ __forceinline__ void upk2(unsigned long long v, float &x, float &y) {
    asm("mov.b64 {%0, %1}, %2;" : "=f"(x), "=f"(y) : "l"(v));
}
#define CP16(dst, src) \
    asm volatile("cp.async.cg.shared.global [%0], [%1], 16;" :: "r"(dst), "l"(src) : "memory")
#define CP_COMMIT asm volatile("cp.async.commit_group;" ::: "memory")
#define CP_WAIT1  asm volatile("cp.async.wait_group 1;" ::: "memory")
#define CP_WAIT0  asm volatile("cp.async.wait_group 0;" ::: "memory")
#define BAR_T asm volatile("bar.sync 1, 128;" ::: "memory")
#define BAR_F asm volatile("bar.sync 2, 128;" ::: "memory")

__device__ __forceinline__ void split4(float4 v, uint2& hi, uint2& lo) {
    __half2 h01 = __floats2half2_rn(v.x, v.y);
    __half2 h23 = __floats2half2_rn(v.z, v.w);
    float2 f01 = __half22float2(h01);
    float2 f23 = __half22float2(h23);
    __half2 l01 = __floats2half2_rn((v.x - f01.x) * LO_SCALE, (v.y - f01.y) * LO_SCALE);
    __half2 l23 = __floats2half2_rn((v.z - f23.x) * LO_SCALE, (v.w - f23.y) * LO_SCALE);
    hi.x = *reinterpret_cast<uint32_t*>(&h01);
    hi.y = *reinterpret_cast<uint32_t*>(&h23);
    lo.x = *reinterpret_cast<uint32_t*>(&l01);
    lo.y = *reinterpret_cast<uint32_t*>(&l23);
}

// ---- prepass: transpose fma-slice of W to k-pair-major float2 ----
__global__ void prep_bt(const float* __restrict__ Wg)
{
    int idx = blockIdx.x * 256 + threadIdx.x;
    if (idx >= KP_F * NE) return;
    int kp = idx >> 6, e = idx & 63;
    const float* row = Wg + (size_t)e * HID + K_T + 2 * kp;
    g_Bt[(size_t)kp * NE + e] = make_float2(row[0], row[1]);
}

__global__ void __launch_bounds__(NTHREADS, 1)
router_fused(const float* __restrict__ X, const float* __restrict__ Wg,
             float* __restrict__ out)
{
    extern __shared__ char smem[];
    const uint32_t sb = smem_u32(smem);
    const int tid  = threadIdx.x;
    const int lane = tid & 31;
    const int wid  = tid >> 5;
    const int bid  = blockIdx.x;
    const int t0   = bid * TM;

    float* shp   = (float*)(smem + SM_RED);
    float* shcnt = shp + NE;
    float* shz   = shp + 2 * NE;
    if (tid < NE) { shp[tid] = 0.f; shcnt[tid] = 0.f; }
    if (tid == 0) shz[0] = 0.f;

    float    accF[2][8][4];
    uint32_t accC[2][8][2];
    unsigned long long accD[4][16];

    if (wid < 4) {
        // ================= TENSOR WARPS (one per SMSP) =================
        const int ptid = tid;                // 0..127
        const int mg   = wid * 32;           // 32 tokens, all 64 experts
#pragma unroll
        for (int mt = 0; mt < 2; mt++)
#pragma unroll
            for (int nt = 0; nt < 8; nt++) {
#pragma unroll
                for (int k = 0; k < 4; k++) accF[mt][nt][k] = 0.f;
                accC[mt][nt][0] = 0u; accC[mt][nt][1] = 0u;
            }

        const float4* Xv = reinterpret_cast<const float4*>(X);
        const float4* Wv = reinterpret_cast<const float4*>(Wg);
        int arow[8], ac4[8], brow[4], bc4[4];
#pragma unroll
        for (int i = 0; i < 8; i++) { int x = ptid + 128 * i; arow[i] = x >> 3; ac4[i] = x & 7; }
#pragma unroll
        for (int i = 0; i < 4; i++) { int x = ptid + 128 * i; brow[i] = x >> 3; bc4[i] = x & 7; }
        float4 stA[8], stB[4];

        auto LOADt = [&](int kt) {
#pragma unroll
            for (int i = 0; i < 8; i++)
                stA[i] = Xv[(size_t)(t0 + arow[i]) * (HID / 4) + kt * 8 + ac4[i]];
#pragma unroll
            for (int i = 0; i < 4; i++)
                stB[i] = Wv[(size_t)brow[i] * (HID / 4) + kt * 8 + bc4[i]];
        };
        auto STSt = [&](int buf) {
            char* bp = smem + T_OFF + buf * T_BUF;
            uint2* pAH = (uint2*)(bp + TA_HI);
            uint2* pAL = (uint2*)(bp + TA_LO);
            uint2* pBH = (uint2*)(bp + TB_HI);
            uint2* pBL = (uint2*)(bp + TB_LO);
#pragma unroll
            for (int i = 0; i < 8; i++) {
                uint2 h, l; split4(stA[i], h, l);
                int o = arow[i] * 10 + ac4[i];
                pAH[o] = h; pAL[o] = l;
            }
#pragma unroll
            for (int i = 0; i < 4; i++) {
                uint2 h, l; split4(stB[i], h, l);
                int o = brow[i] * 10 + bc4[i];
                pBH[o] = h; pBL[o] = l;
            }
        };

        const uint32_t aoff = (uint32_t)(mg + (lane & 15)) * 80 + ((lane >> 4) & 1) * 16;
        const int bmat = lane >> 3;
        uint32_t boff[4];
#pragma unroll
        for (int j = 0; j < 4; j++)
            boff[j] = (uint32_t)(j * 16 + (bmat >> 1) * 8 + (lane & 7)) * 80 + (bmat & 1) * 16;

        auto COMPUTEt = [&](int buf) {
            const uint32_t bb = sb + T_OFF + buf * T_BUF;
#pragma unroll
            for (int kc = 0; kc < 2; kc++) {
                const uint32_t ko = kc * 32;
                uint32_t ah[8], al[8], bh[16], bl[16];
                LDSM4(ah,     bb + TA_HI + aoff + ko);
                LDSM4(ah + 4, bb + TA_HI + aoff + ko + 16 * 80);
                LDSM4(al,     bb + TA_LO + aoff + ko);
                LDSM4(al + 4, bb + TA_LO + aoff + ko + 16 * 80);
#pragma unroll
                for (int j = 0; j < 4; j++) {
                    LDSM4(bh + 4 * j, bb + TB_HI + boff[j] + ko);
                    LDSM4(bl + 4 * j, bb + TB_LO + boff[j] + ko);
                }
#pragma unroll
                for (int mt = 0; mt < 2; mt++)
#pragma unroll
                    for (int nt = 0; nt < 8; nt++)
                        mma_f32(accF[mt][nt], ah + 4 * mt, bh + 2 * nt);
#pragma unroll
                for (int mt = 0; mt < 2; mt++)
#pragma unroll
                    for (int nt = 0; nt < 8; nt++)
                        mma_f16(accC[mt][nt], ah + 4 * mt, bl + 2 * nt);
#pragma unroll
                for (int mt = 0; mt < 2; mt++)
#pragma unroll
                    for (int nt = 0; nt < 8; nt++)
                        mma_f16(accC[mt][nt], al + 4 * mt, bh + 2 * nt);
            }
        };

        LOADt(0); STSt(0); BAR_T;
        for (int kt = 0; kt < NT_T; kt++) {
            const int buf = kt & 1;
            if (kt + 1 < NT_T) LOADt(kt + 1);
            COMPUTEt(buf);
            if (kt + 1 < NT_T) STSt(buf ^ 1);
            BAR_T;
        }
    } else {
        // ================= FMA WARPS (one per SMSP) =================
        const int ptid = tid - 128;          // 0..127
        const int mg2  = (wid - 4) * 32;     // this warp's 32 tokens
        const int g    = lane & 7;           // token group of 4
        const int eg   = lane >> 3;          // expert group of 16
#pragma unroll
        for (int i = 0; i < 4; i++)
#pragma unroll
            for (int j = 0; j < 16; j++) accD[i][j] = 0ull;

        auto issueF = [&](int f, int buf) {
            // A slice: 128 rows x 64 f32 -> 16 chunks/thread
            const uint32_t abase = sb + FA_OFF + buf * FA_BUF;
#pragma unroll
            for (int i = 0; i < 16; i++) {
                int c = ptid + 128 * i;
                int row = c >> 4, off = c & 15;
                CP16(abase + (uint32_t)row * FA_ROW + off * 16,
                     X + (size_t)(t0 + row) * HID + K_T + f * 64 + off * 4);
            }
            // B tile: 32 kp-rows x 64 float2 (swizzled groups) -> 8 chunks/thread
            const uint32_t bbase = sb + FB_OFF + buf * FB_BUF;
#pragma unroll
            for (int i = 0; i < 8; i++) {
                int c = ptid + 128 * i;
                int row = c >> 5, gg = (c >> 3) & 3, q = c & 7;
                CP16(bbase + (uint32_t)row * FB_ROW + gg * 144 + q * 16,
                     g_Bt + (size_t)(f * 32 + row) * NE + gg * 16 + q * 2);
            }
        };

        auto computeF = [&](int buf) {
            const char* pa = smem + FA_OFF + buf * FA_BUF;
            const char* pb = smem + FB_OFF + buf * FB_BUF;
#pragma unroll 2
            for (int kp = 0; kp < 32; kp++) {
                unsigned long long a[4];
#pragma unroll
                for (int i = 0; i < 4; i++)
                    a[i] = *(const unsigned long long*)(pa + (mg2 + g * 4 + i) * FA_ROW + kp * 8);
                unsigned long long b[16];
#pragma unroll
                for (int q = 0; q < 8; q++) {
                    ulonglong2 v = *(const ulonglong2*)(pb + kp * FB_ROW + eg * 144 + q * 16);
                    b[2 * q] = v.x; b[2 * q + 1] = v.y;
                }
#pragma unroll
                for (int i = 0; i < 4; i++)
#pragma unroll
                    for (int j = 0; j < 16; j++)
                        fma2(accD[i][j], a[i], b[j]);
            }
        };

        issueF(0, 0); CP_COMMIT;
        issueF(1, 1); CP_COMMIT;
        CP_WAIT1; BAR_F;
        for (int f = 0; f < NT_F; f++) {
            computeF(f & 1);
            BAR_F;
            if (f + 2 < NT_F) { issueF(f + 2, f & 1); CP_COMMIT; CP_WAIT1; }
            else              { CP_WAIT0; }
            BAR_F;
        }
    }

    __syncthreads();

    // ---- merge: tensor fold stores, fma fold adds ----
    float* Ls = (float*)(smem + LS_OFF);   // [128][65]
    if (wid < 4) {
        const int mg = wid * 32;
        const int r = lane >> 2;
        const int c = 2 * (lane & 3);
#pragma unroll
        for (int mt = 0; mt < 2; mt++)
#pragma unroll
            for (int nt = 0; nt < 8; nt++) {
                float2 c01 = __half22float2(*reinterpret_cast<__half2*>(&accC[mt][nt][0]));
                float2 c23 = __half22float2(*reinterpret_cast<__half2*>(&accC[mt][nt][1]));
                const int row = mg + mt * 16 + r;
                const int col = nt * 8 + c;
                Ls[row * 65 + col]           = accF[mt][nt][0] + c01.x * LO_UNSCALE;
                Ls[row * 65 + col + 1]       = accF[mt][nt][1] + c01.y * LO_UNSCALE;
                Ls[(row + 8) * 65 + col]     = accF[mt][nt][2] + c23.x * LO_UNSCALE;
                Ls[(row + 8) * 65 + col + 1] = accF[mt][nt][3] + c23.y * LO_UNSCALE;
            }
    }
    __syncthreads();
    if (wid >= 4) {
        const int mg2 = (wid - 4) * 32;
        const int g   = lane & 7;
        const int eg  = lane >> 3;
#pragma unroll
        for (int i = 0; i < 4; i++)
#pragma unroll
            for (int j = 0; j < 16; j++) {
                float x, y;
                upk2(accD[i][j], x, y);
                Ls[(mg2 + g * 4 + i) * 65 + eg * 16 + j] += x + y;
            }
    }
    __syncthreads();

    // ---- per-token epilogue on threads 0..127 ----
    if (tid < TM) {
        const float* row = Ls + tid * 65;
        float l1 = -1e30f, l2 = -1e30f; int i1 = 0, i2 = 0;
#pragma unroll
        for (int e = 0; e < NE; e++) {
            const float v = row[e];
            if (v > l1)      { l2 = l1; i2 = i1; l1 = v; i1 = e; }
            else if (v > l2) { l2 = v; i2 = e; }
        }
        float s = 0.f;
#pragma unroll
        for (int e = 0; e < NE; e++) s += expf(row[e] - l1);
        const float inv_s = 1.f / s;
        const float lse   = l1 + logf(s);

        const float p2   = expf(l2 - l1);
        const float wsum = 1.f + p2;
        const int   gt   = t0 + tid;
        out[2 * gt]                 = 1.f / wsum;
        out[2 * gt + 1]             = p2 / wsum;
        out[2 * N_TOK + 2 * gt]     = (float)i1;
        out[2 * N_TOK + 2 * gt + 1] = (float)i2;

#pragma unroll
        for (int e = 0; e < NE; e++) {
            float v = expf(row[e] - l1) * inv_s;
#pragma unroll
            for (int o = 16; o > 0; o >>= 1) v += __shfl_xor_sync(0xffffffffu, v, o);
            if (lane == 0) atomicAdd(&shp[e], v);
        }
        atomicAdd(&shcnt[i1], 1.f);
        atomicAdd(&shcnt[i2], 1.f);
        float zv = lse * lse;
#pragma unroll
        for (int o = 16; o > 0; o >>= 1) zv += __shfl_xor_sync(0xffffffffu, zv, o);
        if (lane == 0) atomicAdd(shz, zv);
    }
    __syncthreads();

    if (tid < NE) {
        g_Pp[bid * NE + tid] = shp[tid];
        g_cp[bid * NE + tid] = shcnt[tid];
    }
    if (tid == 0) g_zp[bid] = shz[0];
    __threadfence();

    __shared__ unsigned int sLast;
    if (tid == 0) {
        unsigned int r2 = atomicAdd(&g_arrive, 1u);
        sLast = (r2 == (unsigned)(gridDim.x - 1)) ? 1u : 0u;
    }
    __syncthreads();
    if (sLast) {
        __threadfence();
        if (tid == 0) shz[0] = 0.f;
        __syncthreads();
        float fp = 0.f;
        if (tid < NE) {
            float sp = 0.f, sc = 0.f;
            for (int b = 0; b < NBLK; b++) {
                sp += g_Pp[b * NE + tid];
                sc += g_cp[b * NE + tid];
            }
            const float f = sc * (1.f / (N_TOK * 2.f));
            const float P = sp * (1.f / N_TOK);
            fp = f * P;
        }
        if (tid >= 128 && tid < 128 + NBLK)
            atomicAdd(shz, g_zp[tid - 128]);
        if (tid < NE) {
#pragma unroll
            for (int o = 16; o > 0; o >>= 1) fp += __shfl_xor_sync(0xffffffffu, fp, o);
            if (lane == 0) shcnt[wid] = fp;
        }
        __syncthreads();
        if (tid == 0) {
            const float lb = (float)NE * (shcnt[0] + shcnt[1]);
            const float z  = shz[0] * (1.f / N_TOK);
            out[4 * N_TOK] = 0.001f * lb + 0.001f * z;
            g_arrive = 0;   // reset for next graph replay
        }
    }
}

extern "C" void kernel_launch(void* const* d_in, const int* in_sizes, int n_in,
                              void* d_out, int out_size)
{
    (void)in_sizes; (void)n_in; (void)out_size;
    const float* X  = (const float*)d_in[0];
    const float* Wg = (const float*)d_in[1];
    float* out = (float*)d_out;

    cudaFuncSetAttribute(router_fused, cudaFuncAttributeMaxDynamicSharedMemorySize, SMEM_TOTAL);
    prep_bt<<<(KP_F * NE + 255) / 256, 256>>>(Wg);
    router_fused<<<NBLK, NTHREADS, SMEM_TOTAL>>>(X, Wg, out);
}

// round 17
// speedup vs baseline: 1.3208x; 1.3208x over previous
#include <cuda_runtime.h>
#include <cuda_fp16.h>
#include <math.h>
#include <stdint.h>

#define N_TOK    16384
#define HID      4096
#define NE       64
#define TM       128
#define KT       64                  // K-tile (fp32 elements)
#define NKT      (HID/KT)            // 64
#define NTHREADS 256
#define NBLK     (N_TOK/TM)          // 128

#define LO_SCALE   2048.0f
#define LO_UNSCALE (1.0f/2048.0f)

// smem: raw fp32 tiles, 3-stage cp.async pipeline. Row stride 288B (72 f32):
// 72 mod 32 = 8 banks/row step -> conflict-free LDS.64 fragment reads.
#define SM_RED    0
#define ST_OFF    1024
#define A_ROW     288
#define STAGE_A   (TM*A_ROW)         // 36864
#define STAGE_B   (NE*A_ROW)         // 18432
#define STAGE_SZ  (STAGE_A+STAGE_B)  // 55296
#define NSTAGE    3
#define SMEM_TOTAL (ST_OFF + NSTAGE*STAGE_SZ)   // 166912
#define LS_OFF    ST_OFF             // epilogue logits 128 x 65 fp32 (reuse)

__device__ float g_Pp[NBLK * NE];
__device__ float g_cp[NBLK * NE];
__device__ float g_zp[NBLK];
__device__ unsigned int g_arrive = 0;

__device__ __forceinline__ uint32_t smem_u32(const void* p) {
    uint32_t a;
    asm("{ .reg .u64 t; cvta.to.shared.u64 t, %1; cvt.u32.u64 %0, t; }" : "=r"(a) : "l"(p));
    return a;
}
__device__ __forceinline__ void mma_f32(float* c, const uint32_t* a, const uint32_t* b) {
    asm volatile(
        "mma.sync.aligned.m16n8k16.row.col.f32.f16.f16.f32 "
        "{%0,%1,%2,%3}, {%4,%5,%6,%7}, {%8,%9}, {%0,%1,%2,%3};"
        : "+f"(c[0]), "+f"(c[1]), "+f"(c[2]), "+f"(c[3])
        : "r"(a[0]), "r"(a[1]), "r"(a[2]), "r"(a[3]), "r"(b[0]), "r"(b[1]));
}
__device__ __forceinline__ void mma_f16(uint32_t* c, const uint32_t* a, const uint32_t* b) {
    asm volatile(
        "mma.sync.aligned.m16n8k16.row.col.f16.f16.f16.f16 "
        "{%0,%1}, {%2,%3,%4,%5}, {%6,%7}, {%0,%1};"
        : "+r"(c[0]), "+r"(c[1])
        : "r"(a[0]), "r"(a[1]), "r"(a[2]), "r"(a[3]), "r"(b[0]), "r"(b[1]));
}
#define CP16(dst, src) \
    asm volatile("cp.async.cg.shared.global [%0], [%1], 16;" :: "r"(dst), "l"(src) : "memory")
#define CP_COMMIT asm volatile("cp.async.commit_group;" ::: "memory")
#define CP_WAIT1  asm volatile("cp.async.wait_group 1;" ::: "memory")
#define CP_WAIT0  asm volatile("cp.async.wait_group 0;" ::: "memory")

// split an f32 pair into packed f16 hi and scaled f16 lo
__device__ __forceinline__ void cvt_pair(float2 p, uint32_t& h, uint32_t& l) {
    __half2 h2 = __floats2half2_rn(p.x, p.y);
    float2  f  = __half22float2(h2);
    __half2 l2 = __floats2half2_rn((p.x - f.x) * LO_SCALE, (p.y - f.y) * LO_SCALE);
    h = *reinterpret_cast<uint32_t*>(&h2);
    l = *reinterpret_cast<uint32_t*>(&l2);
}

__global__ void __launch_bounds__(NTHREADS, 1)
router_fused(const float* __restrict__ X, const float* __restrict__ Wg,
             float* __restrict__ out)
{
    extern __shared__ char smem[];
    const uint32_t sb = smem_u32(smem);
    const int tid  = threadIdx.x;
    const int lane = tid & 31;
    const int wid  = tid >> 5;
    const int bid  = blockIdx.x;
    const int t0   = bid * TM;
    const int mg   = (wid & 3) * 32;     // warp token base
    const int ng   = (wid >> 2) * 32;    // warp expert base

    float* shp   = (float*)(smem + SM_RED);
    float* shcnt = shp + NE;
    float* shz   = shp + 2 * NE;
    if (tid < NE) { shp[tid] = 0.f; shcnt[tid] = 0.f; }
    if (tid == 0) shz[0] = 0.f;

    // ---- cp.async producers: one commit group per tile, ALL threads issue ----
    auto ISSUE = [&](int kt) {
        const uint32_t st = sb + ST_OFF + (uint32_t)(kt % NSTAGE) * STAGE_SZ;
#pragma unroll
        for (int i = 0; i < 8; i++) {                 // A: 128 rows x 16 chunks
            int c = tid + NTHREADS * i;
            int row = c >> 4, off = c & 15;
            CP16(st + (uint32_t)row * A_ROW + off * 16,
                 X + (size_t)(t0 + row) * HID + kt * KT + off * 4);
        }
#pragma unroll
        for (int i = 0; i < 4; i++) {                 // B: 64 rows x 16 chunks
            int c = tid + NTHREADS * i;
            int row = c >> 4, off = c & 15;
            CP16(st + STAGE_A + (uint32_t)row * A_ROW + off * 16,
                 Wg + (size_t)row * HID + kt * KT + off * 4);
        }
        CP_COMMIT;
    };

    float    accF[2][4][4];
    uint32_t accC[2][4][2];
#pragma unroll
    for (int mt = 0; mt < 2; mt++)
#pragma unroll
        for (int nt = 0; nt < 4; nt++) {
#pragma unroll
            for (int k = 0; k < 4; k++) accF[mt][nt][k] = 0.f;
            accC[mt][nt][0] = 0u; accC[mt][nt][1] = 0u;
        }

    const int arow0 = mg + (lane >> 2);
    const int brow0 = ng + (lane >> 2);
    const int kq    = (lane & 3) * 8;    // byte offset of this lane's k-pair

    auto COMPUTE = [&](int kt) {
        const char* st = smem + ST_OFF + (size_t)(kt % NSTAGE) * STAGE_SZ;
#pragma unroll
        for (int kc = 0; kc < 4; kc++) {
            const int kb = kc * 64 + kq;
            uint32_t ah[8], al[8], bh[8], bl[8];
#pragma unroll
            for (int mt = 0; mt < 2; mt++) {
                const char* base = st + (size_t)(arow0 + 16 * mt) * A_ROW + kb;
                float2 p0 = *reinterpret_cast<const float2*>(base);
                float2 p1 = *reinterpret_cast<const float2*>(base + 8 * A_ROW);
                float2 p2 = *reinterpret_cast<const float2*>(base + 32);
                float2 p3 = *reinterpret_cast<const float2*>(base + 8 * A_ROW + 32);
                cvt_pair(p0, ah[4 * mt + 0], al[4 * mt + 0]);
                cvt_pair(p1, ah[4 * mt + 1], al[4 * mt + 1]);
                cvt_pair(p2, ah[4 * mt + 2], al[4 * mt + 2]);
                cvt_pair(p3, ah[4 * mt + 3], al[4 * mt + 3]);
            }
#pragma unroll
            for (int nt = 0; nt < 4; nt++) {
                const char* base = st + STAGE_A + (size_t)(brow0 + 8 * nt) * A_ROW + kb;
                float2 q0 = *reinterpret_cast<const float2*>(base);
                float2 q1 = *reinterpret_cast<const float2*>(base + 32);
                cvt_pair(q0, bh[2 * nt],     bl[2 * nt]);
                cvt_pair(q1, bh[2 * nt + 1], bl[2 * nt + 1]);
            }
            // pass-major: 8 independent accumulators back-to-back per pass
#pragma unroll
            for (int mt = 0; mt < 2; mt++)
#pragma unroll
                for (int nt = 0; nt < 4; nt++)
                    mma_f32(accF[mt][nt], ah + 4 * mt, bh + 2 * nt);
#pragma unroll
            for (int mt = 0; mt < 2; mt++)
#pragma unroll
                for (int nt = 0; nt < 4; nt++)
                    mma_f16(accC[mt][nt], ah + 4 * mt, bl + 2 * nt);
#pragma unroll
            for (int mt = 0; mt < 2; mt++)
#pragma unroll
                for (int nt = 0; nt < 4; nt++)
                    mma_f16(accC[mt][nt], al + 4 * mt, bh + 2 * nt);
        }
    };

    // ---- 3-stage pipeline: wait(kt) -> bar -> issue(kt+2 into freed stage) -> compute(kt)
    ISSUE(0);
    ISSUE(1);
    for (int kt = 0; kt < NKT; kt++) {
        if (kt == NKT - 1) { CP_WAIT0; } else { CP_WAIT1; }
        __syncthreads();
        if (kt + 2 < NKT) ISSUE(kt + 2);
        COMPUTE(kt);
    }
    __syncthreads();

    // fold f16 cross terms into fp32 logits [128][65]
    float* Ls = (float*)(smem + LS_OFF);
    {
        const int r = lane >> 2;
        const int c = 2 * (lane & 3);
#pragma unroll
        for (int mt = 0; mt < 2; mt++)
#pragma unroll
            for (int nt = 0; nt < 4; nt++) {
                float2 c01 = __half22float2(*reinterpret_cast<__half2*>(&accC[mt][nt][0]));
                float2 c23 = __half22float2(*reinterpret_cast<__half2*>(&accC[mt][nt][1]));
                const int row = mg + mt * 16 + r;
                const int col = ng + nt * 8 + c;
                Ls[row * 65 + col]           = accF[mt][nt][0] + c01.x * LO_UNSCALE;
                Ls[row * 65 + col + 1]       = accF[mt][nt][1] + c01.y * LO_UNSCALE;
                Ls[(row + 8) * 65 + col]     = accF[mt][nt][2] + c23.x * LO_UNSCALE;
                Ls[(row + 8) * 65 + col + 1] = accF[mt][nt][3] + c23.y * LO_UNSCALE;
            }
    }
    __syncthreads();

    // per-token epilogue on threads 0..127
    if (tid < TM) {
        const float* row = Ls + tid * 65;
        float l1 = -1e30f, l2 = -1e30f; int i1 = 0, i2 = 0;
#pragma unroll
        for (int e = 0; e < NE; e++) {
            const float v = row[e];
            if (v > l1)      { l2 = l1; i2 = i1; l1 = v; i1 = e; }
            else if (v > l2) { l2 = v; i2 = e; }
        }
        float s = 0.f;
#pragma unroll
        for (int e = 0; e < NE; e++) s += expf(row[e] - l1);
        const float inv_s = 1.f / s;
        const float lse   = l1 + logf(s);

        const float p2   = expf(l2 - l1);
        const float wsum = 1.f + p2;
        const int   gt   = t0 + tid;
        out[2 * gt]                 = 1.f / wsum;
        out[2 * gt + 1]             = p2 / wsum;
        out[2 * N_TOK + 2 * gt]     = (float)i1;
        out[2 * N_TOK + 2 * gt + 1] = (float)i2;

#pragma unroll
        for (int e = 0; e < NE; e++) {
            float v = expf(row[e] - l1) * inv_s;
#pragma unroll
            for (int o = 16; o > 0; o >>= 1) v += __shfl_xor_sync(0xffffffffu, v, o);
            if (lane == 0) atomicAdd(&shp[e], v);
        }
        atomicAdd(&shcnt[i1], 1.f);
        atomicAdd(&shcnt[i2], 1.f);
        float zv = lse * lse;
#pragma unroll
        for (int o = 16; o > 0; o >>= 1) zv += __shfl_xor_sync(0xffffffffu, zv, o);
        if (lane == 0) atomicAdd(shz, zv);
    }
    __syncthreads();

    if (tid < NE) {
        g_Pp[bid * NE + tid] = shp[tid];
        g_cp[bid * NE + tid] = shcnt[tid];
    }
    if (tid == 0) g_zp[bid] = shz[0];
    __threadfence();

    __shared__ unsigned int sLast;
    if (tid == 0) {
        unsigned int r2 = atomicAdd(&g_arrive, 1u);
        sLast = (r2 == (unsigned)(gridDim.x - 1)) ? 1u : 0u;
    }
    __syncthreads();
    if (sLast) {
        __threadfence();
        if (tid == 0) shz[0] = 0.f;
        __syncthreads();
        float fp = 0.f;
        if (tid < NE) {
            float sp = 0.f, sc = 0.f;
            for (int b = 0; b < NBLK; b++) {
                sp += g_Pp[b * NE + tid];
                sc += g_cp[b * NE + tid];
            }
            const float f = sc * (1.f / (N_TOK * 2.f));
            const float P = sp * (1.f / N_TOK);
            fp = f * P;
        }
        if (tid >= 128 && tid < 128 + NBLK)
            atomicAdd(shz, g_zp[tid - 128]);
        if (tid < NE) {
#pragma unroll
            for (int o = 16; o > 0; o >>= 1) fp += __shfl_xor_sync(0xffffffffu, fp, o);
            if (lane == 0) shcnt[wid] = fp;
        }
        __syncthreads();
        if (tid == 0) {
            const float lb = (float)NE * (shcnt[0] + shcnt[1]);
            const float z  = shz[0] * (1.f / N_TOK);
            out[4 * N_TOK] = 0.001f * lb + 0.001f * z;
            g_arrive = 0;   // reset for next graph replay
        }
    }
}

extern "C" void kernel_launch(void* const* d_in, const int* in_sizes, int n_in,
                              void* d_out, int out_size)
{
    (void)in_sizes; (void)n_in; (void)out_size;
    const float* X  = (const float*)d_in[0];
    const float* Wg = (const float*)d_in[1];
    float* out = (float*)d_out;

    cudaFuncSetAttribute(router_fused, cudaFuncAttributeMaxDynamicSharedMemorySize, SMEM_TOTAL);
    router_fused<<<NBLK, NTHREADS, SMEM_TOTAL>>>(X, Wg, out);
}